// round 9
// baseline (speedup 1.0000x reference)
#include <cuda_runtime.h>
#include <cuda_fp16.h>
#include <math.h>
#include <stdint.h>

#define N_TOK   4096
#define CDIM    256
#define HID     128
#define NHEADS  4
#define DHEAD   32
#define QKV_M   384
#define TDIM    512
#define QSCALE2 (0.17677669529663687f * 1.4426950408889634f)  // 32^-0.5 * log2(e)
#define C2OFF   5.7707801635558537f           // 4 * log2(e)
#define FULLMASK 0xffffffffu

// ---------------- scratch (static device globals; no allocation) -------------
__device__ float  g_s1[2 * CDIM];
__device__ float  g_shift[2 * CDIM];
__device__ __half g_xh[2 * N_TOK * CDIM];    // x transposed [b][n][c], half
__device__ __half g_woh[CDIM * HID];         // w_out half
__device__ __half g_q[8 * N_TOK * DHEAD];    // [bh][n][d], scaled QSCALE*log2e
// K+V pre-fragmentized per 64-key tile: [bh][tile][4096 words]
__device__ __align__(16) uint32_t g_kvf[8 * 64 * 4096];
// split-K flash partials
__device__ float  g_po[2 * 8 * N_TOK * DHEAD];
__device__ float  g_l [2 * 8 * N_TOK];

// ======================= helpers =============================================
__device__ __forceinline__ void mma16(float* d, uint32_t a0, uint32_t a1,
                                      uint32_t a2, uint32_t a3,
                                      uint32_t b0, uint32_t b1) {
    asm volatile(
        "mma.sync.aligned.m16n8k16.row.col.f32.f16.f16.f32 "
        "{%0,%1,%2,%3}, {%4,%5,%6,%7}, {%8,%9}, {%0,%1,%2,%3};"
        : "+f"(d[0]), "+f"(d[1]), "+f"(d[2]), "+f"(d[3])
        : "r"(a0), "r"(a1), "r"(a2), "r"(a3), "r"(b0), "r"(b1));
}
__device__ __forceinline__ uint32_t packh2(float lo, float hi) {
    uint32_t u;
    asm("cvt.rn.f16x2.f32 %0, %1, %2;" : "=r"(u) : "f"(hi), "f"(lo));
    return u;
}
__device__ __forceinline__ float ex2(float x) {
    float y;
    asm("ex2.approx.ftz.f32 %0, %1;" : "=f"(y) : "f"(x));
    return y;
}
__device__ __forceinline__ uint32_t smem_u32(const void* p) {
    uint32_t a;
    asm("{ .reg .u64 t; cvta.to.shared.u64 t, %1; cvt.u32.u64 %0, t; }"
        : "=r"(a) : "l"(p));
    return a;
}
__device__ __forceinline__ void cpa16(uint32_t saddr, const void* gptr) {
    asm volatile("cp.async.cg.shared.global [%0], [%1], 16;"
                 :: "r"(saddr), "l"(gptr) : "memory");
}

// ---------------- 1) fused prep: xh transpose | w_out->half | FiLM MLP --------
// blocks [0,512): 64x64 transpose tiles; [512,528): w_out; [528,656): FiLM
__global__ void fused_prep(const float* __restrict__ x,
                           const float* __restrict__ te,
                           const float* __restrict__ w_mlp,
                           const float* __restrict__ b_mlp,
                           const float* __restrict__ w_out) {
    __shared__ float t[64][65];
    const int bid = blockIdx.x;
    const int tid = threadIdx.x;

    if (bid < 512) {
        int b   = bid >> 8;
        int rem = bid & 255;
        int c0  = (rem >> 6) * 64;
        int n0  = (rem & 63) * 64;
        int r = tid >> 4, q = tid & 15;
        const float* xb = x + ((size_t)b * CDIM + c0 + r) * N_TOK + n0 + q * 4;
#pragma unroll
        for (int i = 0; i < 4; i++) {
            float4 v = *(const float4*)(xb + (size_t)(16 * i) * N_TOK);
            int c = r + 16 * i;
            t[q * 4 + 0][c] = v.x;
            t[q * 4 + 1][c] = v.y;
            t[q * 4 + 2][c] = v.z;
            t[q * 4 + 3][c] = v.w;
        }
        __syncthreads();
        int n = tid >> 2, cj = (tid & 3) * 16;
        const float* row = &t[n][cj];
        uint4 u0, u1;
        u0.x = packh2(row[0],  row[1]);  u0.y = packh2(row[2],  row[3]);
        u0.z = packh2(row[4],  row[5]);  u0.w = packh2(row[6],  row[7]);
        u1.x = packh2(row[8],  row[9]);  u1.y = packh2(row[10], row[11]);
        u1.z = packh2(row[12], row[13]); u1.w = packh2(row[14], row[15]);
        __half* dst = g_xh + ((size_t)b * N_TOK + n0 + n) * CDIM + c0 + cj;
        ((uint4*)dst)[0] = u0;
        ((uint4*)dst)[1] = u1;
    } else if (bid < 528) {
        int i = (bid - 512) * 256 + tid;
        if (i < CDIM * HID / 8) {
            const float4* s = (const float4*)w_out;
            float4 a = s[i * 2], c = s[i * 2 + 1];
            uint4 u;
            u.x = packh2(a.x, a.y);  u.y = packh2(a.z, a.w);
            u.z = packh2(c.x, c.y);  u.w = packh2(c.z, c.w);
            ((uint4*)g_woh)[i] = u;
        }
    } else {
        int gw   = (bid - 528) * 8 + (tid >> 5);
        int lane = tid & 31;
        if (gw >= 2 * 2 * CDIM) return;
        int b = gw / (2 * CDIM);
        int j = gw % (2 * CDIM);
        const float* e = te + b * TDIM;
        const float* wr = w_mlp + (size_t)j * TDIM;
        float s = 0.f;
        for (int i = lane; i < TDIM; i += 32) {
            float xx = e[i];
            float si = xx / (1.f + __expf(-xx));
            s += si * wr[i];
        }
#pragma unroll
        for (int o = 16; o; o >>= 1) s += __shfl_xor_sync(FULLMASK, s, o);
        if (lane == 0) {
            float tt = s + b_mlp[j];
            if (j < CDIM) g_s1[b * CDIM + j] = tt + 1.f;
            else          g_shift[b * CDIM + (j - CDIM)] = tt;
        }
    }
}

// ---------------- 2) QKV GEMM: FiLM + bias folded into A staging ---------------
__global__ __launch_bounds__(256) void qkv_mma(const float* __restrict__ w_qkv) {
    __shared__ __align__(16) char smraw[33792];   // frag 12KB | epi 64x132 f32
    uint2* frag = (uint2*)smraw;
    float* smC  = (float*)smraw;
    __shared__ float biasS[64];
    __shared__ float s1S[CDIM], shS[CDIM];

    const int tid = threadIdx.x, lane = tid & 31, wid = tid >> 5;
    const int g = lane >> 2, t = lane & 3;
    const int b = blockIdx.z, o0 = blockIdx.y * 64, n0 = blockIdx.x * 128;

    s1S[tid] = g_s1[b * CDIM + tid];
    shS[tid] = g_shift[b * CDIM + tid];
    __syncthreads();

    // staging roles
    const float* srcA = nullptr;
    const __half* srcB = nullptr;
    uint32_t dsti = 0;
    if (tid < 64) {
        int r = tid;
        srcA = w_qkv + (size_t)(o0 + r) * CDIM;
        dsti = ((r >> 4) * 2 + ((r & 15) >> 3)) * 32 + (r & 7) * 4;
    } else if (tid < 192) {
        int n = tid - 64;
        srcB = g_xh + ((size_t)b * N_TOK + n0 + n) * CDIM;
        dsti = 256 + (n >> 3) * 32 + (n & 7) * 4;
    }
    // prologue prefetch (chunk 0)
    float4 w0, w1, w2, w3;
    uint4 lo, hi;
    if (tid < 64) {
        w0 = *(const float4*)(srcA);     w1 = *(const float4*)(srcA + 4);
        w2 = *(const float4*)(srcA + 8); w3 = *(const float4*)(srcA + 12);
    } else if (tid < 192) {
        lo = *(const uint4*)srcB; hi = *(const uint4*)(srcB + 8);
    }

    float acc[8][4] = {};
    float biasacc = 0.f;
    const int mrow = wid & 3, nhalf = wid >> 2;

    for (int kc = 0; kc < 16; kc++) {
        uint2* buf = frag + (kc & 1) * 768;
        if (tid < 64) {
            const float* s1p = s1S + kc * 16;
            const float* shp = shS + kc * 16;
            float f[16] = {w0.x, w0.y, w0.z, w0.w, w1.x, w1.y, w1.z, w1.w,
                           w2.x, w2.y, w2.z, w2.w, w3.x, w3.y, w3.z, w3.w};
#pragma unroll
            for (int i = 0; i < 16; i++) {
                biasacc += f[i] * shp[i];
                f[i] *= s1p[i];
            }
            uint4* dp = (uint4*)(buf + dsti);
            dp[0] = make_uint4(packh2(f[0], f[1]),  packh2(f[8], f[9]),
                               packh2(f[2], f[3]),  packh2(f[10], f[11]));
            dp[1] = make_uint4(packh2(f[4], f[5]),  packh2(f[12], f[13]),
                               packh2(f[6], f[7]),  packh2(f[14], f[15]));
        } else if (tid < 192) {
            uint4* dp = (uint4*)(buf + dsti);
            dp[0] = make_uint4(lo.x, hi.x, lo.y, hi.y);
            dp[1] = make_uint4(lo.z, hi.z, lo.w, hi.w);
        }
        __syncthreads();
        if (kc < 15) {
            if (tid < 64) {
                srcA += 16;
                w0 = *(const float4*)(srcA);     w1 = *(const float4*)(srcA + 4);
                w2 = *(const float4*)(srcA + 8); w3 = *(const float4*)(srcA + 12);
            } else if (tid < 192) {
                srcB += 16;
                lo = *(const uint4*)srcB; hi = *(const uint4*)(srcB + 8);
            }
        }
        uint2 a02 = buf[(mrow * 2 + 0) * 32 + lane];
        uint2 a13 = buf[(mrow * 2 + 1) * 32 + lane];
#pragma unroll
        for (int j = 0; j < 8; j++) {
            uint2 bb = buf[256 + (nhalf * 8 + j) * 32 + lane];
            mma16(acc[j], a02.x, a13.x, a02.y, a13.y, bb.x, bb.y);
        }
    }
    __syncthreads();   // frag -> smC alias

    float* rowp = smC + (mrow * 16 + g) * 132 + nhalf * 64 + 2 * t;
#pragma unroll
    for (int j = 0; j < 8; j++) {
        rowp[j * 8]               = acc[j][0];
        rowp[j * 8 + 1]           = acc[j][1];
        rowp[8 * 132 + j * 8]     = acc[j][2];
        rowp[8 * 132 + j * 8 + 1] = acc[j][3];
    }
    if (tid < 64) biasS[tid] = biasacc;
    __syncthreads();

    const int kind  = o0 >> 7;            // 0=q,1=k,2=v (uniform per block)
    const int hbase = (o0 >> 5) & 3;
    if (kind == 0) {
#pragma unroll
        for (int i = 0; i < 16; i++) {
            int idx = tid + i * 256;
            int dp = idx & 31, n = idx >> 5;
            int hh = dp >> 4, dpp = dp & 15;
            int r = hh * 32 + dpp * 2;
            float v0 = (smC[r * 132 + n] + biasS[r]) * QSCALE2;
            float v1 = (smC[(r + 1) * 132 + n] + biasS[r + 1]) * QSCALE2;
            int h = hbase + hh;
            *(uint32_t*)(g_q + ((size_t)(b * NHEADS + h) * N_TOK + n0 + n) * DHEAD + dpp * 2)
                = packh2(v0, v1);
        }
    } else if (kind == 1) {
#pragma unroll
        for (int i = 0; i < 16; i++) {
            int idx = tid + i * 256;
            int dp = idx & 31, n = idx >> 5;
            int hh = dp >> 4, dpp = dp & 15;
            int r = hh * 32 + dpp * 2;
            float v0 = smC[r * 132 + n] + biasS[r];
            float v1 = smC[(r + 1) * 132 + n] + biasS[r + 1];
            int bh = b * NHEADS + hbase + hh;
            int ng = n0 + n;
            int tile = ng >> 6, kn = ng & 63;
            int jj = kn >> 3, gg = kn & 7;
            int kk = dpp >> 3, p = dpp & 7, c = p & 3, comp = p >> 2;
            g_kvf[((size_t)bh * 64 + tile) * 4096
                  + (((jj * 2 + kk) * 32 + gg * 4 + c) * 2 + comp)] = packh2(v0, v1);
        }
    } else {
#pragma unroll
        for (int i = 0; i < 16; i++) {
            int idx = tid + i * 256;
            int np = idx & 63, r = idx >> 6;
            int n = np * 2;
            float bias = biasS[r];
            float v0 = smC[r * 132 + n] + bias;
            float v1 = smC[r * 132 + n + 1] + bias;
            int o = o0 + r, h = (o >> 5) & 3, d = o & 31;
            int bh = b * NHEADS + h;
            int ng = n0 + n;
            int tile = ng >> 6, kn = ng & 63;
            int kk = kn >> 4, rr = kn & 15, p = rr >> 1, c = p & 3, comp = p >> 2;
            int blk = (d >> 3) * 4 + kk, ln = (d & 7) * 4 + c;
            g_kvf[((size_t)bh * 64 + tile) * 4096 + 2048
                  + ((blk * 32 + ln) * 2 + comp)] = packh2(v0, v1);
        }
    }
}

// ---------------- 3) flash attention: cp.async 3-stage, 4 blocks/SM ------------
__global__ __launch_bounds__(256, 4) void flash_mma() {
    __shared__ __align__(16) uint32_t frag[3 * 4096];   // 3 stages x 16KB

    const int tid  = threadIdx.x;
    const int lane = tid & 31, wid = tid >> 5;
    const int g    = lane >> 2, tig = lane & 3;
    const int bh   = blockIdx.y;
    const int q0   = blockIdx.x * 128;
    const int sp   = blockIdx.z;

    const uint32_t sbase = smem_u32(frag) + tid * 16;
    const uint32_t* gsrc = g_kvf + ((size_t)bh * 64 + sp * 32) * 4096 + tid * 4;

#pragma unroll
    for (int s = 0; s < 2; s++) {
#pragma unroll
        for (int j = 0; j < 4; j++)
            cpa16(sbase + s * 16384 + j * 4096, gsrc + (size_t)s * 4096 + j * 1024);
        asm volatile("cp.async.commit_group;" ::: "memory");
    }

    uint32_t qa[2][4];
    const int qrow = q0 + wid * 16 + g;
    {
        const __half* Qg = g_q + (size_t)bh * N_TOK * DHEAD;
#pragma unroll
        for (int kk = 0; kk < 2; kk++) {
            const __half* base = Qg + (size_t)qrow * DHEAD + kk * 16 + 2 * tig;
            qa[kk][0] = *(const uint32_t*)(base);
            qa[kk][1] = *(const uint32_t*)(base + 8 * DHEAD);
            qa[kk][2] = *(const uint32_t*)(base + 8);
            qa[kk][3] = *(const uint32_t*)(base + 8 * DHEAD + 8);
        }
    }

    float o[4][4] = {};
    float l0 = 0.f, l1 = 0.f;

    for (int kt = 0; kt < 32; kt++) {
        asm volatile("cp.async.wait_group 1;" ::: "memory");
        __syncthreads();
        {
            int tt = kt + 2;
            if (tt < 32) {
                int st = tt % 3;
#pragma unroll
                for (int j = 0; j < 4; j++)
                    cpa16(sbase + st * 16384 + j * 4096,
                          gsrc + (size_t)tt * 4096 + j * 1024);
            }
            asm volatile("cp.async.commit_group;" ::: "memory");
        }

        const uint2* kb = (const uint2*)(frag + (kt % 3) * 4096);
        const uint2* vb = kb + 1024;

#pragma unroll
        for (int half = 0; half < 2; half++) {
            float s[4][4];
#pragma unroll
            for (int j4 = 0; j4 < 4; j4++) {
                s[j4][0] = 0.f; s[j4][1] = 0.f; s[j4][2] = 0.f; s[j4][3] = 0.f;
                int jj = half * 4 + j4;
#pragma unroll
                for (int kk = 0; kk < 2; kk++) {
                    uint2 bf = kb[(jj * 2 + kk) * 32 + lane];
                    mma16(s[j4], qa[kk][0], qa[kk][1], qa[kk][2], qa[kk][3], bf.x, bf.y);
                }
            }
#pragma unroll
            for (int kkp = 0; kkp < 2; kkp++) {
                float p00 = ex2(s[2 * kkp][0] - C2OFF);
                float p01 = ex2(s[2 * kkp][1] - C2OFF);
                float p02 = ex2(s[2 * kkp][2] - C2OFF);
                float p03 = ex2(s[2 * kkp][3] - C2OFF);
                float p10 = ex2(s[2 * kkp + 1][0] - C2OFF);
                float p11 = ex2(s[2 * kkp + 1][1] - C2OFF);
                float p12 = ex2(s[2 * kkp + 1][2] - C2OFF);
                float p13 = ex2(s[2 * kkp + 1][3] - C2OFF);
                l0 += (p00 + p01) + (p10 + p11);
                l1 += (p02 + p03) + (p12 + p13);
                uint32_t a0 = packh2(p00, p01);
                uint32_t a1 = packh2(p02, p03);
                uint32_t a2 = packh2(p10, p11);
                uint32_t a3 = packh2(p12, p13);
                int kkv = half * 2 + kkp;
#pragma unroll
                for (int n = 0; n < 4; n++) {
                    uint2 bb = vb[(n * 4 + kkv) * 32 + lane];
                    mma16(o[n], a0, a1, a2, a3, bb.x, bb.y);
                }
            }
        }
    }

    l0 += __shfl_xor_sync(FULLMASK, l0, 1);
    l0 += __shfl_xor_sync(FULLMASK, l0, 2);
    l1 += __shfl_xor_sync(FULLMASK, l1, 1);
    l1 += __shfl_xor_sync(FULLMASK, l1, 2);

    const int sb = sp * 8 + bh;
    float* po = g_po + ((size_t)sb * N_TOK + qrow) * DHEAD;
#pragma unroll
    for (int n = 0; n < 4; n++) {
        int d0 = n * 8 + 2 * tig;
        *(float2*)(po + d0)             = make_float2(o[n][0], o[n][1]);
        *(float2*)(po + 8 * DHEAD + d0) = make_float2(o[n][2], o[n][3]);
    }
    if (tig == 0) {
        g_l[(size_t)sb * N_TOK + qrow]     = l0;
        g_l[(size_t)sb * N_TOK + qrow + 8] = l1;
    }
}

// ---------------- 4) output projection: split-K combine fused into B staging ---
__global__ __launch_bounds__(256) void out_mma(const float* __restrict__ b_out,
                                               float* __restrict__ out) {
    __shared__ __align__(16) uint2 frag[2 * 768];

    const int tid = threadIdx.x, lane = tid & 31, wid = tid >> 5;
    const int g = lane >> 2, t = lane & 3;
    const int b = blockIdx.z, o0 = blockIdx.y * 64, n0 = blockIdx.x * 128;

    // staging roles
    const __half* srcA = nullptr;
    uint32_t dsti = 0;
    int nn = 0;
    float inv[4];
    if (tid < 64) {
        int r = tid;
        srcA = g_woh + (size_t)(o0 + r) * HID;
        dsti = ((r >> 4) * 2 + ((r & 15) >> 3)) * 32 + (r & 7) * 4;
    } else if (tid < 192) {
        int n = tid - 64;
        nn = n0 + n;
        dsti = 256 + (n >> 3) * 32 + (n & 7) * 4;
#pragma unroll
        for (int h = 0; h < 4; h++) {
            int bh = b * NHEADS + h;
            inv[h] = 1.f / (g_l[(size_t)bh * N_TOK + nn]
                          + g_l[(size_t)(8 + bh) * N_TOK + nn]);
        }
    }

    // prologue prefetch (kc = 0)
    uint4 lo, hi;
    float4 pa[4], pb[4];
    if (tid < 64) {
        lo = *(const uint4*)srcA; hi = *(const uint4*)(srcA + 8);
    } else if (tid < 192) {
        const float* p0 = g_po + ((size_t)(b * NHEADS) * N_TOK + nn) * DHEAD;
        const float* p1 = g_po + ((size_t)(8 + b * NHEADS) * N_TOK + nn) * DHEAD;
#pragma unroll
        for (int i = 0; i < 4; i++) {
            pa[i] = *(const float4*)(p0 + i * 4);
            pb[i] = *(const float4*)(p1 + i * 4);
        }
    }

    float acc[8][4] = {};
    const int mrow = wid & 3, nhalf = wid >> 2;

    for (int kc = 0; kc < 8; kc++) {
        uint2* buf = frag + (kc & 1) * 768;
        if (tid < 64) {
            uint4* dp = (uint4*)(buf + dsti);
            dp[0] = make_uint4(lo.x, hi.x, lo.y, hi.y);
            dp[1] = make_uint4(lo.z, hi.z, lo.w, hi.w);
        } else if (tid < 192) {
            float iv = inv[kc >> 1];
            float f[16];
#pragma unroll
            for (int i = 0; i < 4; i++) {
                f[4 * i + 0] = (pa[i].x + pb[i].x) * iv;
                f[4 * i + 1] = (pa[i].y + pb[i].y) * iv;
                f[4 * i + 2] = (pa[i].z + pb[i].z) * iv;
                f[4 * i + 3] = (pa[i].w + pb[i].w) * iv;
            }
            uint4* dp = (uint4*)(buf + dsti);
            dp[0] = make_uint4(packh2(f[0], f[1]),  packh2(f[8], f[9]),
                               packh2(f[2], f[3]),  packh2(f[10], f[11]));
            dp[1] = make_uint4(packh2(f[4], f[5]),  packh2(f[12], f[13]),
                               packh2(f[6], f[7]),  packh2(f[14], f[15]));
        }
        __syncthreads();
        if (kc < 7) {
            if (tid < 64) {
                srcA += 16;
                lo = *(const uint4*)srcA; hi = *(const uint4*)(srcA + 8);
            } else if (tid < 192) {
                int kn = kc + 1;
                int h = kn >> 1, d0 = (kn & 1) * 16;
                const float* p0 = g_po + ((size_t)(b * NHEADS + h) * N_TOK + nn) * DHEAD + d0;
                const float* p1 = g_po + ((size_t)(8 + b * NHEADS + h) * N_TOK + nn) * DHEAD + d0;
#pragma unroll
                for (int i = 0; i < 4; i++) {
                    pa[i] = *(const float4*)(p0 + i * 4);
                    pb[i] = *(const float4*)(p1 + i * 4);
                }
            }
        }
        uint2 a02 = buf[(mrow * 2 + 0) * 32 + lane];
        uint2 a13 = buf[(mrow * 2 + 1) * 32 + lane];
#pragma unroll
        for (int j = 0; j < 8; j++) {
            uint2 bb = buf[256 + (nhalf * 8 + j) * 32 + lane];
            mma16(acc[j], a02.x, a13.x, a02.y, a13.y, bb.x, bb.y);
        }
    }

    const int orow = o0 + mrow * 16 + g;
    const float bias0 = b_out[orow], bias1 = b_out[orow + 8];
    float* dst0 = out + ((size_t)b * CDIM + orow) * N_TOK + n0 + nhalf * 64 + 2 * t;
    float* dst1 = dst0 + 8 * N_TOK;
#pragma unroll
    for (int j = 0; j < 8; j++) {
        *(float2*)(dst0 + j * 8) = make_float2(acc[j][0] + bias0, acc[j][1] + bias0);
        *(float2*)(dst1 + j * 8) = make_float2(acc[j][2] + bias1, acc[j][3] + bias1);
    }
}

// ---------------- launch -------------------------------------------------------
extern "C" void kernel_launch(void* const* d_in, const int* in_sizes, int n_in,
                              void* d_out, int out_size) {
    const float* x      = (const float*)d_in[0];
    const float* te     = (const float*)d_in[1];
    const float* w_mlp  = (const float*)d_in[2];
    const float* b_mlp  = (const float*)d_in[3];
    const float* w_qkv  = (const float*)d_in[4];
    const float* w_out  = (const float*)d_in[5];
    const float* b_out  = (const float*)d_in[6];
    float* out = (float*)d_out;

    fused_prep<<<656, 256>>>(x, te, w_mlp, b_mlp, w_out);
    qkv_mma<<<dim3(32, 6, 2), 256>>>(w_qkv);
    flash_mma<<<dim3(32, 8, 2), 256>>>();
    out_mma<<<dim3(32, 4, 2), 256>>>(b_out, out);
}

// round 10
// speedup vs baseline: 1.0870x; 1.0870x over previous
#include <cuda_runtime.h>
#include <cuda_fp16.h>
#include <math.h>
#include <stdint.h>

#define N_TOK   4096
#define CDIM    256
#define HID     128
#define NHEADS  4
#define DHEAD   32
#define QKV_M   384
#define TDIM    512
#define QSCALE2 (0.17677669529663687f * 1.4426950408889634f)  // 32^-0.5 * log2(e)
#define C2OFF   5.7707801635558537f           // 4 * log2(e)
#define FULLMASK 0xffffffffu

// ---------------- scratch (static device globals; no allocation) -------------
__device__ float  g_s1[2 * CDIM];
__device__ float  g_shift[2 * CDIM];
__device__ __half g_xh[2 * N_TOK * CDIM];    // x transposed [b][n][c], half
__device__ __half g_woh[CDIM * HID];         // w_out half
__device__ __half g_q[8 * N_TOK * DHEAD];    // [bh][n][d], scaled QSCALE*log2e
// K+V pre-fragmentized per 64-key tile: [bh][tile][2048 words]
//   words 0..1023  : K fragments, words 1024..2047 : V fragments
__device__ __align__(16) uint32_t g_kvf[8 * 64 * 2048];
__device__ __half g_aoh[2 * N_TOK * HID];    // attn out [b][n][h*32+d], half
// split-K flash partials
__device__ float  g_po[2 * 8 * N_TOK * DHEAD];
__device__ float  g_l [2 * 8 * N_TOK];

// ======================= helpers =============================================
__device__ __forceinline__ void mma16(float* d, uint32_t a0, uint32_t a1,
                                      uint32_t a2, uint32_t a3,
                                      uint32_t b0, uint32_t b1) {
    asm volatile(
        "mma.sync.aligned.m16n8k16.row.col.f32.f16.f16.f32 "
        "{%0,%1,%2,%3}, {%4,%5,%6,%7}, {%8,%9}, {%0,%1,%2,%3};"
        : "+f"(d[0]), "+f"(d[1]), "+f"(d[2]), "+f"(d[3])
        : "r"(a0), "r"(a1), "r"(a2), "r"(a3), "r"(b0), "r"(b1));
}
__device__ __forceinline__ uint32_t packh2(float lo, float hi) {
    uint32_t u;
    asm("cvt.rn.f16x2.f32 %0, %1, %2;" : "=r"(u) : "f"(hi), "f"(lo));
    return u;
}
__device__ __forceinline__ float ex2(float x) {
    float y;
    asm("ex2.approx.ftz.f32 %0, %1;" : "=f"(y) : "f"(x));
    return y;
}
__device__ __forceinline__ uint32_t smem_u32(const void* p) {
    uint32_t a;
    asm("{ .reg .u64 t; cvta.to.shared.u64 t, %1; cvt.u32.u64 %0, t; }"
        : "=r"(a) : "l"(p));
    return a;
}
__device__ __forceinline__ void cpa16(uint32_t saddr, const void* gptr) {
    asm volatile("cp.async.cg.shared.global [%0], [%1], 16;"
                 :: "r"(saddr), "l"(gptr) : "memory");
}

// ---------------- 1) fused prep: xh transpose | w_out->half | FiLM MLP --------
__global__ void fused_prep(const float* __restrict__ x,
                           const float* __restrict__ te,
                           const float* __restrict__ w_mlp,
                           const float* __restrict__ b_mlp,
                           const float* __restrict__ w_out) {
    __shared__ float t[64][65];
    const int bid = blockIdx.x;
    const int tid = threadIdx.x;

    if (bid < 512) {
        int b   = bid >> 8;
        int rem = bid & 255;
        int c0  = (rem >> 6) * 64;
        int n0  = (rem & 63) * 64;
        int r = tid >> 4, q = tid & 15;
        const float* xb = x + ((size_t)b * CDIM + c0 + r) * N_TOK + n0 + q * 4;
#pragma unroll
        for (int i = 0; i < 4; i++) {
            float4 v = *(const float4*)(xb + (size_t)(16 * i) * N_TOK);
            int c = r + 16 * i;
            t[q * 4 + 0][c] = v.x;
            t[q * 4 + 1][c] = v.y;
            t[q * 4 + 2][c] = v.z;
            t[q * 4 + 3][c] = v.w;
        }
        __syncthreads();
        int n = tid >> 2, cj = (tid & 3) * 16;
        const float* row = &t[n][cj];
        uint4 u0, u1;
        u0.x = packh2(row[0],  row[1]);  u0.y = packh2(row[2],  row[3]);
        u0.z = packh2(row[4],  row[5]);  u0.w = packh2(row[6],  row[7]);
        u1.x = packh2(row[8],  row[9]);  u1.y = packh2(row[10], row[11]);
        u1.z = packh2(row[12], row[13]); u1.w = packh2(row[14], row[15]);
        __half* dst = g_xh + ((size_t)b * N_TOK + n0 + n) * CDIM + c0 + cj;
        ((uint4*)dst)[0] = u0;
        ((uint4*)dst)[1] = u1;
    } else if (bid < 528) {
        int i = (bid - 512) * 256 + tid;
        if (i < CDIM * HID / 8) {
            const float4* s = (const float4*)w_out;
            float4 a = s[i * 2], c = s[i * 2 + 1];
            uint4 u;
            u.x = packh2(a.x, a.y);  u.y = packh2(a.z, a.w);
            u.z = packh2(c.x, c.y);  u.w = packh2(c.z, c.w);
            ((uint4*)g_woh)[i] = u;
        }
    } else {
        int gw   = (bid - 528) * 8 + (tid >> 5);
        int lane = tid & 31;
        if (gw >= 2 * 2 * CDIM) return;
        int b = gw / (2 * CDIM);
        int j = gw % (2 * CDIM);
        const float* e = te + b * TDIM;
        const float* wr = w_mlp + (size_t)j * TDIM;
        float s = 0.f;
        for (int i = lane; i < TDIM; i += 32) {
            float xx = e[i];
            float si = xx / (1.f + __expf(-xx));
            s += si * wr[i];
        }
#pragma unroll
        for (int o = 16; o; o >>= 1) s += __shfl_xor_sync(FULLMASK, s, o);
        if (lane == 0) {
            float tt = s + b_mlp[j];
            if (j < CDIM) g_s1[b * CDIM + j] = tt + 1.f;
            else          g_shift[b * CDIM + (j - CDIM)] = tt;
        }
    }
}

// ---------------- 2) QKV GEMM: FiLM + bias folded into A staging ---------------
__global__ __launch_bounds__(256) void qkv_mma(const float* __restrict__ w_qkv) {
    __shared__ __align__(16) char smraw[33792];   // frag 12KB | epi 64x132 f32
    uint2* frag = (uint2*)smraw;
    float* smC  = (float*)smraw;
    __shared__ float biasS[64];
    __shared__ float s1S[CDIM], shS[CDIM];

    const int tid = threadIdx.x, lane = tid & 31, wid = tid >> 5;
    const int g = lane >> 2, t = lane & 3;
    const int b = blockIdx.z, o0 = blockIdx.y * 64, n0 = blockIdx.x * 128;

    s1S[tid] = g_s1[b * CDIM + tid];
    shS[tid] = g_shift[b * CDIM + tid];
    __syncthreads();

    const float* srcA = nullptr;
    const __half* srcB = nullptr;
    uint32_t dsti = 0;
    if (tid < 64) {
        int r = tid;
        srcA = w_qkv + (size_t)(o0 + r) * CDIM;
        dsti = ((r >> 4) * 2 + ((r & 15) >> 3)) * 32 + (r & 7) * 4;
    } else if (tid < 192) {
        int n = tid - 64;
        srcB = g_xh + ((size_t)b * N_TOK + n0 + n) * CDIM;
        dsti = 256 + (n >> 3) * 32 + (n & 7) * 4;
    }
    float4 w0, w1, w2, w3;
    uint4 lo, hi;
    if (tid < 64) {
        w0 = *(const float4*)(srcA);     w1 = *(const float4*)(srcA + 4);
        w2 = *(const float4*)(srcA + 8); w3 = *(const float4*)(srcA + 12);
    } else if (tid < 192) {
        lo = *(const uint4*)srcB; hi = *(const uint4*)(srcB + 8);
    }

    float acc[8][4] = {};
    float biasacc = 0.f;
    const int mrow = wid & 3, nhalf = wid >> 2;

    for (int kc = 0; kc < 16; kc++) {
        uint2* buf = frag + (kc & 1) * 768;
        if (tid < 64) {
            const float* s1p = s1S + kc * 16;
            const float* shp = shS + kc * 16;
            float f[16] = {w0.x, w0.y, w0.z, w0.w, w1.x, w1.y, w1.z, w1.w,
                           w2.x, w2.y, w2.z, w2.w, w3.x, w3.y, w3.z, w3.w};
#pragma unroll
            for (int i = 0; i < 16; i++) {
                biasacc += f[i] * shp[i];
                f[i] *= s1p[i];
            }
            uint4* dp = (uint4*)(buf + dsti);
            dp[0] = make_uint4(packh2(f[0], f[1]),  packh2(f[8], f[9]),
                               packh2(f[2], f[3]),  packh2(f[10], f[11]));
            dp[1] = make_uint4(packh2(f[4], f[5]),  packh2(f[12], f[13]),
                               packh2(f[6], f[7]),  packh2(f[14], f[15]));
        } else if (tid < 192) {
            uint4* dp = (uint4*)(buf + dsti);
            dp[0] = make_uint4(lo.x, hi.x, lo.y, hi.y);
            dp[1] = make_uint4(lo.z, hi.z, lo.w, hi.w);
        }
        __syncthreads();
        if (kc < 15) {
            if (tid < 64) {
                srcA += 16;
                w0 = *(const float4*)(srcA);     w1 = *(const float4*)(srcA + 4);
                w2 = *(const float4*)(srcA + 8); w3 = *(const float4*)(srcA + 12);
            } else if (tid < 192) {
                srcB += 16;
                lo = *(const uint4*)srcB; hi = *(const uint4*)(srcB + 8);
            }
        }
        uint2 a02 = buf[(mrow * 2 + 0) * 32 + lane];
        uint2 a13 = buf[(mrow * 2 + 1) * 32 + lane];
#pragma unroll
        for (int j = 0; j < 8; j++) {
            uint2 bb = buf[256 + (nhalf * 8 + j) * 32 + lane];
            mma16(acc[j], a02.x, a13.x, a02.y, a13.y, bb.x, bb.y);
        }
    }
    __syncthreads();   // frag -> smC alias

    float* rowp = smC + (mrow * 16 + g) * 132 + nhalf * 64 + 2 * t;
#pragma unroll
    for (int j = 0; j < 8; j++) {
        rowp[j * 8]               = acc[j][0];
        rowp[j * 8 + 1]           = acc[j][1];
        rowp[8 * 132 + j * 8]     = acc[j][2];
        rowp[8 * 132 + j * 8 + 1] = acc[j][3];
    }
    if (tid < 64) biasS[tid] = biasacc;
    __syncthreads();

    const int kind  = o0 >> 7;            // 0=q,1=k,2=v (uniform per block)
    const int hbase = (o0 >> 5) & 3;
    if (kind == 0) {
#pragma unroll
        for (int i = 0; i < 16; i++) {
            int idx = tid + i * 256;
            int dp = idx & 31, n = idx >> 5;
            int hh = dp >> 4, dpp = dp & 15;
            int r = hh * 32 + dpp * 2;
            float v0 = (smC[r * 132 + n] + biasS[r]) * QSCALE2;
            float v1 = (smC[(r + 1) * 132 + n] + biasS[r + 1]) * QSCALE2;
            int h = hbase + hh;
            *(uint32_t*)(g_q + ((size_t)(b * NHEADS + h) * N_TOK + n0 + n) * DHEAD + dpp * 2)
                = packh2(v0, v1);
        }
    } else if (kind == 1) {
        // K: words 0..1023 of the 2048-word tile
#pragma unroll
        for (int i = 0; i < 16; i++) {
            int idx = tid + i * 256;
            int dp = idx & 31, n = idx >> 5;
            int hh = dp >> 4, dpp = dp & 15;
            int r = hh * 32 + dpp * 2;
            float v0 = smC[r * 132 + n] + biasS[r];
            float v1 = smC[(r + 1) * 132 + n] + biasS[r + 1];
            int bh = b * NHEADS + hbase + hh;
            int ng = n0 + n;
            int tile = ng >> 6, kn = ng & 63;
            int jj = kn >> 3, gg = kn & 7;
            int kk = dpp >> 3, p = dpp & 7, c = p & 3, comp = p >> 2;
            g_kvf[((size_t)bh * 64 + tile) * 2048
                  + (((jj * 2 + kk) * 32 + gg * 4 + c) * 2 + comp)] = packh2(v0, v1);
        }
    } else {
        // V: words 1024..2047 of the tile
#pragma unroll
        for (int i = 0; i < 16; i++) {
            int idx = tid + i * 256;
            int np = idx & 63, r = idx >> 6;
            int n = np * 2;
            float bias = biasS[r];
            float v0 = smC[r * 132 + n] + bias;
            float v1 = smC[r * 132 + n + 1] + bias;
            int o = o0 + r, h = (o >> 5) & 3, d = o & 31;
            int bh = b * NHEADS + h;
            int ng = n0 + n;
            int tile = ng >> 6, kn = ng & 63;
            int kk = kn >> 4, rr = kn & 15, p = rr >> 1, c = p & 3, comp = p >> 2;
            int blk = (d >> 3) * 4 + kk, ln = (d & 7) * 4 + c;
            g_kvf[((size_t)bh * 64 + tile) * 2048 + 1024
                  + ((blk * 32 + ln) * 2 + comp)] = packh2(v0, v1);
        }
    }
}

// ---------------- 3) flash attention: cp.async 3-stage (8KB tiles) -------------
__global__ __launch_bounds__(256, 4) void flash_mma() {
    __shared__ __align__(16) uint32_t frag[3 * 2048];   // 3 stages x 8KB

    const int tid  = threadIdx.x;
    const int lane = tid & 31, wid = tid >> 5;
    const int g    = lane >> 2, tig = lane & 3;
    const int bh   = blockIdx.y;
    const int q0   = blockIdx.x * 128;
    const int sp   = blockIdx.z;

    const uint32_t sbase = smem_u32(frag) + tid * 16;
    const uint32_t* gsrc = g_kvf + ((size_t)bh * 64 + sp * 32) * 2048 + tid * 4;

    // prologue: stages 0,1 (tiles 0,1); 2 x 16B per thread per tile
#pragma unroll
    for (int s = 0; s < 2; s++) {
#pragma unroll
        for (int j = 0; j < 2; j++)
            cpa16(sbase + s * 8192 + j * 4096, gsrc + (size_t)s * 2048 + j * 1024);
        asm volatile("cp.async.commit_group;" ::: "memory");
    }

    uint32_t qa[2][4];
    const int qrow = q0 + wid * 16 + g;
    {
        const __half* Qg = g_q + (size_t)bh * N_TOK * DHEAD;
#pragma unroll
        for (int kk = 0; kk < 2; kk++) {
            const __half* base = Qg + (size_t)qrow * DHEAD + kk * 16 + 2 * tig;
            qa[kk][0] = *(const uint32_t*)(base);
            qa[kk][1] = *(const uint32_t*)(base + 8 * DHEAD);
            qa[kk][2] = *(const uint32_t*)(base + 8);
            qa[kk][3] = *(const uint32_t*)(base + 8 * DHEAD + 8);
        }
    }

    float o[4][4] = {};
    float l0 = 0.f, l1 = 0.f;

    for (int kt = 0; kt < 32; kt++) {
        asm volatile("cp.async.wait_group 1;" ::: "memory");
        __syncthreads();
        {
            int tt = kt + 2;
            if (tt < 32) {
                int st = tt % 3;
#pragma unroll
                for (int j = 0; j < 2; j++)
                    cpa16(sbase + st * 8192 + j * 4096,
                          gsrc + (size_t)tt * 2048 + j * 1024);
            }
            asm volatile("cp.async.commit_group;" ::: "memory");
        }

        const uint2* kb = (const uint2*)(frag + (kt % 3) * 2048);
        const uint2* vb = kb + 512;

#pragma unroll
        for (int half = 0; half < 2; half++) {
            float s[4][4];
#pragma unroll
            for (int j4 = 0; j4 < 4; j4++) {
                s[j4][0] = 0.f; s[j4][1] = 0.f; s[j4][2] = 0.f; s[j4][3] = 0.f;
                int jj = half * 4 + j4;
#pragma unroll
                for (int kk = 0; kk < 2; kk++) {
                    uint2 bf = kb[(jj * 2 + kk) * 32 + lane];
                    mma16(s[j4], qa[kk][0], qa[kk][1], qa[kk][2], qa[kk][3], bf.x, bf.y);
                }
            }
#pragma unroll
            for (int kkp = 0; kkp < 2; kkp++) {
                float p00 = ex2(s[2 * kkp][0] - C2OFF);
                float p01 = ex2(s[2 * kkp][1] - C2OFF);
                float p02 = ex2(s[2 * kkp][2] - C2OFF);
                float p03 = ex2(s[2 * kkp][3] - C2OFF);
                float p10 = ex2(s[2 * kkp + 1][0] - C2OFF);
                float p11 = ex2(s[2 * kkp + 1][1] - C2OFF);
                float p12 = ex2(s[2 * kkp + 1][2] - C2OFF);
                float p13 = ex2(s[2 * kkp + 1][3] - C2OFF);
                l0 += (p00 + p01) + (p10 + p11);
                l1 += (p02 + p03) + (p12 + p13);
                uint32_t a0 = packh2(p00, p01);
                uint32_t a1 = packh2(p02, p03);
                uint32_t a2 = packh2(p10, p11);
                uint32_t a3 = packh2(p12, p13);
                int kkv = half * 2 + kkp;
#pragma unroll
                for (int n = 0; n < 4; n++) {
                    uint2 bb = vb[(n * 4 + kkv) * 32 + lane];
                    mma16(o[n], a0, a1, a2, a3, bb.x, bb.y);
                }
            }
        }
    }

    l0 += __shfl_xor_sync(FULLMASK, l0, 1);
    l0 += __shfl_xor_sync(FULLMASK, l0, 2);
    l1 += __shfl_xor_sync(FULLMASK, l1, 1);
    l1 += __shfl_xor_sync(FULLMASK, l1, 2);

    const int sb = sp * 8 + bh;
    float* po = g_po + ((size_t)sb * N_TOK + qrow) * DHEAD;
#pragma unroll
    for (int n = 0; n < 4; n++) {
        int d0 = n * 8 + 2 * tig;
        *(float2*)(po + d0)             = make_float2(o[n][0], o[n][1]);
        *(float2*)(po + 8 * DHEAD + d0) = make_float2(o[n][2], o[n][3]);
    }
    if (tig == 0) {
        g_l[(size_t)sb * N_TOK + qrow]     = l0;
        g_l[(size_t)sb * N_TOK + qrow + 8] = l1;
    }
}

// ---------------- 3b) combine the 2 splits -> g_aoh ----------------------------
__global__ void combine_k(void) {
    int idx = blockIdx.x * blockDim.x + threadIdx.x;   // 262144 threads
    int row = idx >> 3;
    int d0  = (idx & 7) * 4;
    int bh = row >> 12, n = row & (N_TOK - 1);
    size_t b0 = (size_t)bh * N_TOK + n;
    size_t b1 = (size_t)(8 + bh) * N_TOK + n;
    float inv = 1.f / (g_l[b0] + g_l[b1]);
    float4 p0 = *(const float4*)(g_po + b0 * DHEAD + d0);
    float4 p1 = *(const float4*)(g_po + b1 * DHEAD + d0);
    float v0 = (p0.x + p1.x) * inv;
    float v1 = (p0.y + p1.y) * inv;
    float v2 = (p0.z + p1.z) * inv;
    float v3 = (p0.w + p1.w) * inv;
    int b = bh >> 2, h = bh & 3;
    __half* dst = g_aoh + ((size_t)b * N_TOK + n) * HID + h * 32 + d0;
    *(uint32_t*)(dst)     = packh2(v0, v1);
    *(uint32_t*)(dst + 2) = packh2(v2, v3);
}

// ---------------- 4) output projection: f16 mma --------------------------------
__global__ __launch_bounds__(256) void out_mma(const float* __restrict__ b_out,
                                               float* __restrict__ out) {
    __shared__ __align__(16) uint2 frag[2 * 768];

    const int tid = threadIdx.x, lane = tid & 31, wid = tid >> 5;
    const int g = lane >> 2, t = lane & 3;
    const int b = blockIdx.z, o0 = blockIdx.y * 64, n0 = blockIdx.x * 128;

    const __half* A = g_woh + (size_t)o0 * HID;
    const __half* B = g_aoh + ((size_t)b * N_TOK + n0) * HID;

    const __half* src = nullptr;
    uint32_t dsti = 0;
    bool active = tid < 192;
    if (tid < 64) {
        int r = tid;
        src = A + (size_t)r * HID;
        dsti = ((r >> 4) * 2 + ((r & 15) >> 3)) * 32 + (r & 7) * 4;
    } else if (tid < 192) {
        int n = tid - 64;
        src = B + (size_t)n * HID;
        dsti = 256 + (n >> 3) * 32 + (n & 7) * 4;
    }
    uint4 lo, hi;
    if (active) { lo = *(const uint4*)src; hi = *(const uint4*)(src + 8); }

    float acc[8][4] = {};
    const int mrow = wid & 3, nhalf = wid >> 2;

    for (int kc = 0; kc < 8; kc++) {
        uint2* buf = frag + (kc & 1) * 768;
        if (active) {
            uint4* dp = (uint4*)(buf + dsti);
            dp[0] = make_uint4(lo.x, hi.x, lo.y, hi.y);
            dp[1] = make_uint4(lo.z, hi.z, lo.w, hi.w);
        }
        __syncthreads();
        if (active && kc < 7) {
            src += 16;
            lo = *(const uint4*)src; hi = *(const uint4*)(src + 8);
        }
        uint2 a02 = buf[(mrow * 2 + 0) * 32 + lane];
        uint2 a13 = buf[(mrow * 2 + 1) * 32 + lane];
#pragma unroll
        for (int j = 0; j < 8; j++) {
            uint2 bb = buf[256 + (nhalf * 8 + j) * 32 + lane];
            mma16(acc[j], a02.x, a13.x, a02.y, a13.y, bb.x, bb.y);
        }
    }

    const int orow = o0 + mrow * 16 + g;
    const float bias0 = b_out[orow], bias1 = b_out[orow + 8];
    float* dst0 = out + ((size_t)b * CDIM + orow) * N_TOK + n0 + nhalf * 64 + 2 * t;
    float* dst1 = dst0 + 8 * N_TOK;
#pragma unroll
    for (int j = 0; j < 8; j++) {
        *(float2*)(dst0 + j * 8) = make_float2(acc[j][0] + bias0, acc[j][1] + bias0);
        *(float2*)(dst1 + j * 8) = make_float2(acc[j][2] + bias1, acc[j][3] + bias1);
    }
}

// ---------------- launch -------------------------------------------------------
extern "C" void kernel_launch(void* const* d_in, const int* in_sizes, int n_in,
                              void* d_out, int out_size) {
    const float* x      = (const float*)d_in[0];
    const float* te     = (const float*)d_in[1];
    const float* w_mlp  = (const float*)d_in[2];
    const float* b_mlp  = (const float*)d_in[3];
    const float* w_qkv  = (const float*)d_in[4];
    const float* w_out  = (const float*)d_in[5];
    const float* b_out  = (const float*)d_in[6];
    float* out = (float*)d_out;

    fused_prep<<<656, 256>>>(x, te, w_mlp, b_mlp, w_out);
    qkv_mma<<<dim3(32, 6, 2), 256>>>(w_qkv);
    flash_mma<<<dim3(32, 8, 2), 256>>>();
    combine_k<<<1024, 256>>>();
    out_mma<<<dim3(32, 4, 2), 256>>>(b_out, out);
}